// round 11
// baseline (speedup 1.0000x reference)
#include <cuda_runtime.h>
#include <cuda_bf16.h>
#include <math.h>

#define BB   64
#define TT   256
#define HH   1024
#define PP   128
#define LL   256
#define GG   4096
#define MTOT 16384
#define NCTA 128

// ---------------- device-global scratch (allocation-free contract) ----------------
__device__ float         g_xg [(size_t)MTOT * GG];   // input-transform (per layer, reused)
__device__ __nv_bfloat16 g_xhi[(size_t)MTOT * HH];   // hseq hi (layer output / GEMM A)
__device__ __nv_bfloat16 g_xlo[(size_t)MTOT * HH];
__device__ __nv_bfloat16 g_inhi[(size_t)MTOT * PP];  // layer-0 input
__device__ __nv_bfloat16 g_inlo[(size_t)MTOT * PP];
__device__ __nv_bfloat16 g_whi[(size_t)GG * HH];     // weight split scratch (sequential reuse)
__device__ __nv_bfloat16 g_wlo[(size_t)GG * HH];
__device__ __nv_bfloat16 g_rhi[2][BB * HH];          // recurrent h ring
__device__ __nv_bfloat16 g_rlo[2][BB * HH];
__device__ __nv_bfloat16 g_h0hi[BB * HH];
__device__ __nv_bfloat16 g_h0lo[BB * HH];
__device__ unsigned g_barc;                          // barrier counter (self-resetting)
__device__ unsigned g_barg;                          // barrier generation (monotonic)

__device__ __forceinline__ float sigf(float x) { return 1.0f / (1.0f + __expf(-x)); }

__device__ __forceinline__ void split_bf16(float v, __nv_bfloat16& hi, __nv_bfloat16& lo) {
    hi = __float2bfloat16(v);
    lo = __float2bfloat16(v - __bfloat162float(hi));
}

__device__ __forceinline__ void cp16(void* smem, const void* gmem) {
    unsigned s = (unsigned)__cvta_generic_to_shared(smem);
    asm volatile("cp.async.cg.shared.global [%0], [%1], 16;\n" :: "r"(s), "l"(gmem));
}
#define CP_COMMIT() asm volatile("cp.async.commit_group;\n" ::: "memory")
#define CP_WAIT1()  asm volatile("cp.async.wait_group 1;\n" ::: "memory")
#define CP_WAIT0()  asm volatile("cp.async.wait_group 0;\n" ::: "memory")

__device__ __forceinline__ void mma16816(float* c,
    unsigned a0, unsigned a1, unsigned a2, unsigned a3, unsigned b0, unsigned b1)
{
    asm volatile(
        "mma.sync.aligned.m16n8k16.row.col.f32.bf16.bf16.f32 "
        "{%0,%1,%2,%3},{%4,%5,%6,%7},{%8,%9},{%0,%1,%2,%3};\n"
        : "+f"(c[0]), "+f"(c[1]), "+f"(c[2]), "+f"(c[3])
        : "r"(a0), "r"(a1), "r"(a2), "r"(a3), "r"(b0), "r"(b1));
}

// ldmatrix x4: per-lane address; lanes 0-7 -> tile0 rows, 8-15 -> tile1, 16-23 -> tile2, 24-31 -> tile3
__device__ __forceinline__ void ldsm_x4(unsigned& r0, unsigned& r1, unsigned& r2, unsigned& r3,
                                        const void* p)
{
    unsigned a = (unsigned)__cvta_generic_to_shared(p);
    asm volatile("ldmatrix.sync.aligned.m8n8.x4.shared.b16 {%0,%1,%2,%3}, [%4];\n"
                 : "=r"(r0), "=r"(r1), "=r"(r2), "=r"(r3) : "r"(a));
}

__device__ __forceinline__ void st_cg_b16(__nv_bfloat16* p, __nv_bfloat16 v) {
    unsigned short u = *(unsigned short*)&v;
    asm volatile("st.global.cg.u16 [%0], %1;\n" :: "l"(p), "h"(u));
}

// ---------------- h0 = z @ fc_init_w^T + b ; seed ring[0] ----------------
__global__ void k_init(const float* __restrict__ z, const float* __restrict__ w,
                       const float* __restrict__ bias)
{
    __shared__ float zs[LL];
    int b = blockIdx.y;
    int h = blockIdx.x * 256 + threadIdx.x;
    for (int i = threadIdx.x; i < LL; i += 256) zs[i] = z[b * LL + i];
    __syncthreads();
    const float* wr = w + (size_t)h * LL;
    float acc = bias[h];
    #pragma unroll 8
    for (int k = 0; k < LL; k++) acc += zs[k] * wr[k];
    __nv_bfloat16 hi, lo; split_bf16(acc, hi, lo);
    int idx = b * HH + h;
    g_h0hi[idx] = hi;  g_h0lo[idx] = lo;
    g_rhi[0][idx] = hi; g_rlo[0][idx] = lo;
}

__global__ void k_seed()
{
    int i = blockIdx.x * 256 + threadIdx.x;
    g_rhi[0][i] = g_h0hi[i];
    g_rlo[0][i] = g_h0lo[i];
}

// ---------------- layer-0 input (start token / shifted target) -> bf16 pair ----------------
__global__ void k_convin(const float* __restrict__ tgt, const float* __restrict__ start)
{
    int idx = blockIdx.x * 256 + threadIdx.x;      // over MTOT*PP
    int m = idx >> 7, p = idx & (PP - 1);
    int t = m & (TT - 1);
    float v = (t == 0) ? start[p] : tgt[(size_t)(m - 1) * PP + p];
    __nv_bfloat16 hi, lo; split_bf16(v, hi, lo);
    g_inhi[idx] = hi; g_inlo[idx] = lo;
}

// ---------------- weight matrix -> bf16 pair scratch ----------------
__global__ void k_convw(const float* __restrict__ src, int n)
{
    int i = blockIdx.x * 256 + threadIdx.x;
    if (i < n) {
        __nv_bfloat16 hi, lo; split_bf16(src[i], hi, lo);
        g_whi[i] = hi; g_wlo[i] = lo;
    }
}

// ---------------- split-bf16 GEMM: C[M,N] = act(bias + A[M,K] * B[N,K]^T) ----------------
// BM=64 BN=64 BK=32, 256 threads, 3-pass split, cp.async double buffer, ldmatrix fragments.
template<int ACT>
__global__ __launch_bounds__(256, 2)
void k_bgemm(const __nv_bfloat16* __restrict__ Ahi, const __nv_bfloat16* __restrict__ Alo,
             const __nv_bfloat16* __restrict__ Bhi, const __nv_bfloat16* __restrict__ Blo,
             int K,
             const float* __restrict__ bias1, const float* __restrict__ bias2,
             float* __restrict__ C, int ldc)
{
    __shared__ __align__(16) __nv_bfloat16 sA[2][2][64 * 40];  // [buf][hi/lo][row*40+k]
    __shared__ __align__(16) __nv_bfloat16 sB[2][2][64 * 40];

    int m0 = blockIdx.x * 64, n0 = blockIdx.y * 64;
    int tid = threadIdx.x;
    int lane = tid & 31, w = tid >> 5;
    int g = lane >> 2, tg = lane & 3;
    int m0w = (w & 3) * 16, n0w = (w >> 2) * 32;

    int srow = tid >> 2, sseg = (tid & 3) * 8;
    const __nv_bfloat16* gAh = Ahi + (size_t)(m0 + srow) * K + sseg;
    const __nv_bfloat16* gAl = Alo + (size_t)(m0 + srow) * K + sseg;
    const __nv_bfloat16* gBh = Bhi + (size_t)(n0 + srow) * K + sseg;
    const __nv_bfloat16* gBl = Blo + (size_t)(n0 + srow) * K + sseg;
    int soff = srow * 40 + sseg;

    // ldmatrix lane addressing
    int grp = lane >> 3, lr = lane & 7;
    int aoff = (m0w + (grp & 1) * 8 + lr) * 40 + (grp >> 1) * 8;   // hi half; lo at +64*40
    int boffs[4];
    #pragma unroll
    for (int nt = 0; nt < 4; nt++)
        boffs[nt] = ((grp >= 2) ? 64 * 40 : 0) + (n0w + nt * 8 + lr) * 40 + (grp & 1) * 8;

    float acc[4][4];
    #pragma unroll
    for (int i = 0; i < 4; i++)
        #pragma unroll
        for (int j = 0; j < 4; j++) acc[i][j] = 0.0f;

    int nch = K >> 5;
    cp16(&sA[0][0][soff], gAh); cp16(&sA[0][1][soff], gAl);
    cp16(&sB[0][0][soff], gBh); cp16(&sB[0][1][soff], gBl);
    CP_COMMIT();

    for (int c = 0; c < nch; c++) {
        int buf = c & 1;
        if (c + 1 < nch) {
            int ko = (c + 1) * 32;
            cp16(&sA[buf ^ 1][0][soff], gAh + ko); cp16(&sA[buf ^ 1][1][soff], gAl + ko);
            cp16(&sB[buf ^ 1][0][soff], gBh + ko); cp16(&sB[buf ^ 1][1][soff], gBl + ko);
            CP_COMMIT();
            CP_WAIT1();
        } else {
            CP_WAIT0();
        }
        __syncthreads();

        const __nv_bfloat16* Abase = &sA[buf][0][0];
        const __nv_bfloat16* Bbase = &sB[buf][0][0];
        #pragma unroll
        for (int kk = 0; kk < 2; kk++) {
            unsigned ah0, ah1, ah2, ah3, al0, al1, al2, al3;
            ldsm_x4(ah0, ah1, ah2, ah3, Abase + aoff + kk * 16);
            ldsm_x4(al0, al1, al2, al3, Abase + 64 * 40 + aoff + kk * 16);
            #pragma unroll
            for (int nt = 0; nt < 4; nt++) {
                unsigned bh0, bh1, bl0, bl1;
                ldsm_x4(bh0, bh1, bl0, bl1, Bbase + boffs[nt] + kk * 16);
                mma16816(acc[nt], ah0, ah1, ah2, ah3, bh0, bh1);
                mma16816(acc[nt], al0, al1, al2, al3, bh0, bh1);
                mma16816(acc[nt], ah0, ah1, ah2, ah3, bl0, bl1);
            }
        }
        __syncthreads();
    }

    #pragma unroll
    for (int nt = 0; nt < 4; nt++) {
        int col = n0 + n0w + nt * 8 + tg * 2;
        float b0v = bias1[col]     + (bias2 ? bias2[col]     : 0.0f);
        float b1v = bias1[col + 1] + (bias2 ? bias2[col + 1] : 0.0f);
        float v0 = acc[nt][0] + b0v, v1 = acc[nt][1] + b1v;
        float v2 = acc[nt][2] + b0v, v3 = acc[nt][3] + b1v;
        if (ACT) { v0 = sigf(v0); v1 = sigf(v1); v2 = sigf(v2); v3 = sigf(v3); }
        int r0 = m0 + m0w + g, r1 = r0 + 8;
        *(float2*)&C[(size_t)r0 * ldc + col] = make_float2(v0, v1);
        *(float2*)&C[(size_t)r1 * ldc + col] = make_float2(v2, v3);
    }
}

// ---------------- persistent recurrence: all 256 steps of one layer ----------------
// 128 CTAs (1/SM due to 212KB smem; co-resident). CTA owns h-dims [j0,j0+8) -> 32 gate cols.
// Whh slice bf16 hi/lo resident in SMEM; h ring in global L2 (st.cg / cp.async.cg).
#define WPITCH 1032
#define HPITCH 136
#define SMEM_PERSIST (2*32*WPITCH*2 + 4*64*HPITCH*2 + 64*33*4 + 512*4)

__global__ __launch_bounds__(256, 1)
void k_persist(const float* __restrict__ Whh, const float* __restrict__ xg,
               __nv_bfloat16* __restrict__ rhi, __nv_bfloat16* __restrict__ rlo,
               __nv_bfloat16* __restrict__ shi, __nv_bfloat16* __restrict__ slo)
{
    extern __shared__ char sm_raw[];
    __nv_bfloat16* Wh = (__nv_bfloat16*)sm_raw;           // [32][WPITCH]; Wl right after
    __nv_bfloat16* Wl = Wh + 32 * WPITCH;
    __nv_bfloat16* Hs = Wl + 32 * WPITCH;                 // [buf2][hi/lo][64*HPITCH]
    float* Gs = (float*)(Hs + 4 * 64 * HPITCH);           // [64][33]
    float* Cs = Gs + 64 * 33;                             // [512] cell state

    int tid = threadIdx.x;
    int lane = tid & 31, w = tid >> 5;
    int g = lane >> 2, tg = lane & 3;
    int m0w = (w >> 1) * 16, n0w = (w & 1) * 16;
    int j0 = blockIdx.x * 8;

    // ldmatrix lane addressing (lane-constant)
    int grp = lane >> 3, lr = lane & 7;
    int h_aoff = (m0w + (grp & 1) * 8 + lr) * HPITCH + (grp >> 1) * 8;   // within one 64*HPITCH half
    int w_boff0 = ((grp >= 2) ? 32 * WPITCH : 0) + (n0w + lr) * WPITCH + (grp & 1) * 8;
    int w_boff1 = w_boff0 + 8 * WPITCH;

    // one-time: split W slice into SMEM; zero cell state
    for (int s = tid; s < 32 * 256; s += 256) {
        int n = s >> 8;                 // col 0..31 = gate*8+jj
        int ks = (s & 255) * 4;
        int grow = (n >> 3) * HH + j0 + (n & 7);
        float4 v = *(const float4*)&Whh[(size_t)grow * HH + ks];
        float vv[4] = {v.x, v.y, v.z, v.w};
        #pragma unroll
        for (int q = 0; q < 4; q++) {
            __nv_bfloat16 hi, lo; split_bf16(vv[q], hi, lo);
            Wh[n * WPITCH + ks + q] = hi;
            Wl[n * WPITCH + ks + q] = lo;
        }
    }
    for (int s = tid; s < 512; s += 256) Cs[s] = 0.0f;
    __syncthreads();

    for (int t = 0; t < TT; t++) {
        const __nv_bfloat16* hh = rhi + (size_t)(t & 1) * BB * HH;
        const __nv_bfloat16* hl = rlo + (size_t)(t & 1) * BB * HH;
        __nv_bfloat16* ohh = rhi + (size_t)((t & 1) ^ 1) * BB * HH;
        __nv_bfloat16* ohl = rlo + (size_t)((t & 1) ^ 1) * BB * HH;

        // xg prefetch (overlaps MMA)
        float xv[2][4];
        #pragma unroll
        for (int e = 0; e < 2; e++) {
            int p = tid + e * 256;
            int b = p >> 3, jj = p & 7;
            size_t base = ((size_t)(b * TT + t)) * GG + j0 + jj;
            #pragma unroll
            for (int q = 0; q < 4; q++) xv[e][q] = __ldg(&xg[base + (size_t)q * HH]);
        }

        float acch[2][4], accm[2][4];
        #pragma unroll
        for (int i = 0; i < 2; i++)
            #pragma unroll
            for (int j = 0; j < 4; j++) { acch[i][j] = 0.0f; accm[i][j] = 0.0f; }

        // stage chunk 0
        #pragma unroll
        for (int i = 0; i < 4; i++) {
            int slot = i * 256 + tid;
            int row = slot >> 4, seg = (slot & 15) * 8;
            cp16(&Hs[0 * 64 * HPITCH + row * HPITCH + seg], hh + row * HH + seg);
            cp16(&Hs[1 * 64 * HPITCH + row * HPITCH + seg], hl + row * HH + seg);
        }
        CP_COMMIT();

        for (int c = 0; c < 8; c++) {
            int buf = c & 1;
            if (c < 7) {
                int k0 = (c + 1) * 128;
                #pragma unroll
                for (int i = 0; i < 4; i++) {
                    int slot = i * 256 + tid;
                    int row = slot >> 4, seg = (slot & 15) * 8;
                    cp16(&Hs[((buf ^ 1) * 2 + 0) * 64 * HPITCH + row * HPITCH + seg], hh + row * HH + k0 + seg);
                    cp16(&Hs[((buf ^ 1) * 2 + 1) * 64 * HPITCH + row * HPITCH + seg], hl + row * HH + k0 + seg);
                }
                CP_COMMIT();
                CP_WAIT1();
            } else {
                CP_WAIT0();
            }
            __syncthreads();

            const __nv_bfloat16* Abase = &Hs[(buf * 2 + 0) * 64 * HPITCH];  // hi; lo at +64*HPITCH
            #pragma unroll
            for (int kk = 0; kk < 8; kk++) {
                unsigned ah0, ah1, ah2, ah3, al0, al1, al2, al3;
                ldsm_x4(ah0, ah1, ah2, ah3, Abase + h_aoff + kk * 16);
                ldsm_x4(al0, al1, al2, al3, Abase + 64 * HPITCH + h_aoff + kk * 16);
                int kw = c * 128 + kk * 16;
                unsigned b00, b01, b02, b03, b10, b11, b12, b13;
                ldsm_x4(b00, b01, b02, b03, Wh + w_boff0 + kw);
                ldsm_x4(b10, b11, b12, b13, Wh + w_boff1 + kw);
                // nt=0: hi*hi -> acch, lo*hi + hi*lo -> accm (independent chains)
                mma16816(acch[0], ah0, ah1, ah2, ah3, b00, b01);
                mma16816(accm[0], al0, al1, al2, al3, b00, b01);
                mma16816(accm[0], ah0, ah1, ah2, ah3, b02, b03);
                // nt=1
                mma16816(acch[1], ah0, ah1, ah2, ah3, b10, b11);
                mma16816(accm[1], al0, al1, al2, al3, b10, b11);
                mma16816(accm[1], ah0, ah1, ah2, ah3, b12, b13);
            }
            __syncthreads();
        }

        // stage Whh*h into Gs  (row=batch, col=gate*8+jj)
        #pragma unroll
        for (int nt = 0; nt < 2; nt++) {
            int col = n0w + nt * 8 + tg * 2;
            Gs[(m0w + g) * 33 + col]         = acch[nt][0] + accm[nt][0];
            Gs[(m0w + g) * 33 + col + 1]     = acch[nt][1] + accm[nt][1];
            Gs[(m0w + g + 8) * 33 + col]     = acch[nt][2] + accm[nt][2];
            Gs[(m0w + g + 8) * 33 + col + 1] = acch[nt][3] + accm[nt][3];
        }
        __syncthreads();

        // LSTM cell: 8 h-dims x 64 batches
        #pragma unroll
        for (int e = 0; e < 2; e++) {
            int p = tid + e * 256;
            int b = p >> 3, jj = p & 7;
            float gi = Gs[b * 33 + jj]      + xv[e][0];
            float gf = Gs[b * 33 + 8 + jj]  + xv[e][1];
            float gg = Gs[b * 33 + 16 + jj] + xv[e][2];
            float go = Gs[b * 33 + 24 + jj] + xv[e][3];
            float cc = sigf(gf) * Cs[p] + sigf(gi) * tanhf(gg);
            float h  = sigf(go) * tanhf(cc);
            Cs[p] = cc;
            __nv_bfloat16 hhi, hlo; split_bf16(h, hhi, hlo);
            size_t oidx = (size_t)b * HH + j0 + jj;
            st_cg_b16(ohh + oidx, hhi);
            st_cg_b16(ohl + oidx, hlo);
            size_t sidx = ((size_t)(b * TT + t)) * HH + j0 + jj;
            shi[sidx] = hhi;
            slo[sidx] = hlo;
        }

        // grid barrier (all 128 CTAs resident; generation counter, self-resetting count)
        __syncthreads();
        __threadfence();
        if (tid == 0) {
            unsigned my = *((volatile unsigned*)&g_barg);
            if (atomicAdd(&g_barc, 1u) == NCTA - 1) {
                g_barc = 0;
                __threadfence();
                atomicExch(&g_barg, my + 1);
            } else {
                while (*((volatile unsigned*)&g_barg) == my) __nanosleep(32);
            }
            __threadfence();
        }
        __syncthreads();
    }
}

// ---------------- launch ----------------
extern "C" void kernel_launch(void* const* d_in, const int* in_sizes, int n_in,
                              void* d_out, int out_size)
{
    (void)in_sizes; (void)n_in; (void)out_size;
    const float* z     = (const float*)d_in[0];
    const float* tgt   = (const float*)d_in[1];
    const float* fw    = (const float*)d_in[2];
    const float* fb    = (const float*)d_in[3];
    const float* start = (const float*)d_in[4];
    const float* Wih0  = (const float*)d_in[5];
    const float* Whh0  = (const float*)d_in[6];
    const float* bih0  = (const float*)d_in[7];
    const float* bhh0  = (const float*)d_in[8];
    const float* Wih1  = (const float*)d_in[9];
    const float* Whh1  = (const float*)d_in[10];
    const float* bih1  = (const float*)d_in[11];
    const float* bhh1  = (const float*)d_in[12];
    const float* outw  = (const float*)d_in[13];
    const float* outb  = (const float*)d_in[14];
    float* out = (float*)d_out;

    float* xg_p;
    __nv_bfloat16 *xhi_p, *xlo_p, *inhi_p, *inlo_p, *whi_p, *wlo_p, *rhi_p, *rlo_p;
    cudaGetSymbolAddress((void**)&xg_p,   g_xg);
    cudaGetSymbolAddress((void**)&xhi_p,  g_xhi);
    cudaGetSymbolAddress((void**)&xlo_p,  g_xlo);
    cudaGetSymbolAddress((void**)&inhi_p, g_inhi);
    cudaGetSymbolAddress((void**)&inlo_p, g_inlo);
    cudaGetSymbolAddress((void**)&whi_p,  g_whi);
    cudaGetSymbolAddress((void**)&wlo_p,  g_wlo);
    cudaGetSymbolAddress((void**)&rhi_p,  g_rhi);
    cudaGetSymbolAddress((void**)&rlo_p,  g_rlo);

    cudaFuncSetAttribute(k_persist, cudaFuncAttributeMaxDynamicSharedMemorySize, SMEM_PERSIST);

    // h0 + seed ring; layer-0 input -> bf16 pair
    k_init<<<dim3(HH / 256, BB), 256>>>(z, fw, fb);
    k_convin<<<(MTOT * PP) / 256, 256>>>(tgt, start);

    // layer 0: xg0 = x_in @ Wih0^T + b  -> recurrence
    k_convw<<<(GG * PP + 255) / 256, 256>>>(Wih0, GG * PP);
    k_bgemm<0><<<dim3(MTOT / 64, GG / 64), 256>>>(inhi_p, inlo_p, whi_p, wlo_p, PP,
                                                  bih0, bhh0, xg_p, GG);
    k_persist<<<NCTA, 256, SMEM_PERSIST>>>(Whh0, xg_p, rhi_p, rlo_p, xhi_p, xlo_p);

    // layer 1: xg1 = h1seq @ Wih1^T + b (consumes g_xhi before layer-1 overwrites it)
    k_convw<<<(GG * HH + 255) / 256, 256>>>(Wih1, GG * HH);
    k_bgemm<0><<<dim3(MTOT / 64, GG / 64), 256>>>(xhi_p, xlo_p, whi_p, wlo_p, HH,
                                                  bih1, bhh1, xg_p, GG);
    k_seed<<<(BB * HH) / 256, 256>>>();
    k_persist<<<NCTA, 256, SMEM_PERSIST>>>(Whh1, xg_p, rhi_p, rlo_p, xhi_p, xlo_p);

    // out = sigmoid(h2seq @ out_w^T + out_b)
    k_convw<<<(PP * HH + 255) / 256, 256>>>(outw, PP * HH);
    k_bgemm<1><<<dim3(MTOT / 64, PP / 64), 256>>>(xhi_p, xlo_p, whi_p, wlo_p, HH,
                                                  outb, nullptr, out, PP);
}

// round 12
// speedup vs baseline: 1.1879x; 1.1879x over previous
#include <cuda_runtime.h>
#include <cuda_bf16.h>
#include <math.h>

#define BB   64
#define TT   256
#define HH   1024
#define PP   128
#define LL   256
#define GG   4096
#define MTOT 16384
#define NCTA 128

// ---------------- device-global scratch (allocation-free contract) ----------------
__device__ float         g_xg [(size_t)MTOT * GG];   // input-transform (per layer, reused)
__device__ __nv_bfloat16 g_xhi[(size_t)MTOT * HH];   // hseq hi (layer output / GEMM A)
__device__ __nv_bfloat16 g_xlo[(size_t)MTOT * HH];
__device__ __nv_bfloat16 g_inhi[(size_t)MTOT * PP];  // layer-0 input
__device__ __nv_bfloat16 g_inlo[(size_t)MTOT * PP];
__device__ __nv_bfloat16 g_whi[(size_t)GG * HH];     // weight split scratch (sequential reuse)
__device__ __nv_bfloat16 g_wlo[(size_t)GG * HH];
// recurrent h ring: chunk-blocked + swizzled layout, see ring_off()
__device__ __nv_bfloat16 g_rhi[2][BB * HH];
__device__ __nv_bfloat16 g_rlo[2][BB * HH];
__device__ __nv_bfloat16 g_h0hi[BB * HH];            // linear layout
__device__ __nv_bfloat16 g_h0lo[BB * HH];
__device__ unsigned g_barc;                          // barrier counter (self-resetting)
__device__ unsigned g_barg;                          // barrier generation (monotonic)

__device__ __forceinline__ float sigf(float x) { return 1.0f / (1.0f + __expf(-x)); }

__device__ __forceinline__ void split_bf16(float v, __nv_bfloat16& hi, __nv_bfloat16& lo) {
    hi = __float2bfloat16(v);
    lo = __float2bfloat16(v - __bfloat162float(hi));
}

// ring element offset for (batch b, h-index j): blocked per 128-col chunk, XOR-swizzled
// within the 64x256B chunk tile so a linear bulk copy into SMEM (256B row pitch)
// yields conflict-free ldmatrix phases.
__device__ __forceinline__ size_t ring_off(int b, int j) {
    int chunk = j >> 7, cw = j & 127;
    int byte = (cw * 2) ^ ((b & 7) << 4);
    return (size_t)chunk * 8192 + b * 128 + (byte >> 1);
}

__device__ __forceinline__ void cp16(void* smem, const void* gmem) {
    unsigned s = (unsigned)__cvta_generic_to_shared(smem);
    asm volatile("cp.async.cg.shared.global [%0], [%1], 16;\n" :: "r"(s), "l"(gmem));
}
#define CP_COMMIT() asm volatile("cp.async.commit_group;\n" ::: "memory")
#define CP_WAIT1()  asm volatile("cp.async.wait_group 1;\n" ::: "memory")
#define CP_WAIT0()  asm volatile("cp.async.wait_group 0;\n" ::: "memory")

__device__ __forceinline__ void mma16816(float* c,
    unsigned a0, unsigned a1, unsigned a2, unsigned a3, unsigned b0, unsigned b1)
{
    asm volatile(
        "mma.sync.aligned.m16n8k16.row.col.f32.bf16.bf16.f32 "
        "{%0,%1,%2,%3},{%4,%5,%6,%7},{%8,%9},{%0,%1,%2,%3};\n"
        : "+f"(c[0]), "+f"(c[1]), "+f"(c[2]), "+f"(c[3])
        : "r"(a0), "r"(a1), "r"(a2), "r"(a3), "r"(b0), "r"(b1));
}

__device__ __forceinline__ void ldsm_x4(unsigned& r0, unsigned& r1, unsigned& r2, unsigned& r3,
                                        const void* p)
{
    unsigned a = (unsigned)__cvta_generic_to_shared(p);
    asm volatile("ldmatrix.sync.aligned.m8n8.x4.shared.b16 {%0,%1,%2,%3}, [%4];\n"
                 : "=r"(r0), "=r"(r1), "=r"(r2), "=r"(r3) : "r"(a));
}

__device__ __forceinline__ void st_cg_b16(__nv_bfloat16* p, __nv_bfloat16 v) {
    unsigned short u = *(unsigned short*)&v;
    asm volatile("st.global.cg.u16 [%0], %1;\n" :: "l"(p), "h"(u));
}

// ---- mbarrier + bulk-async helpers ----
__device__ __forceinline__ void mbar_init(unsigned a, unsigned cnt) {
    asm volatile("mbarrier.init.shared.b64 [%0], %1;" :: "r"(a), "r"(cnt) : "memory");
}
__device__ __forceinline__ void mbar_expect(unsigned a, unsigned bytes) {
    asm volatile("mbarrier.arrive.expect_tx.shared.b64 _, [%0], %1;" :: "r"(a), "r"(bytes) : "memory");
}
__device__ __forceinline__ void mbar_wait(unsigned a, unsigned parity) {
    asm volatile(
        "{\n\t.reg .pred P;\n\t"
        "WL%=:\n\t"
        "mbarrier.try_wait.parity.shared::cta.b64 P, [%0], %1;\n\t"
        "@P bra WD%=;\n\t"
        "bra WL%=;\n\t"
        "WD%=:\n\t}"
        :: "r"(a), "r"(parity) : "memory");
}
__device__ __forceinline__ void bulkcp(unsigned dst, const void* src, unsigned bytes, unsigned mbar) {
    asm volatile(
        "cp.async.bulk.shared::cluster.global.mbarrier::complete_tx::bytes [%0], [%1], %2, [%3];"
        :: "r"(dst), "l"(src), "r"(bytes), "r"(mbar) : "memory");
}

// ---------------- h0 = z @ fc_init_w^T + b ; seed ring[0] ----------------
__global__ void k_init(const float* __restrict__ z, const float* __restrict__ w,
                       const float* __restrict__ bias)
{
    __shared__ float zs[LL];
    int b = blockIdx.y;
    int h = blockIdx.x * 256 + threadIdx.x;
    for (int i = threadIdx.x; i < LL; i += 256) zs[i] = z[b * LL + i];
    __syncthreads();
    const float* wr = w + (size_t)h * LL;
    float acc = bias[h];
    #pragma unroll 8
    for (int k = 0; k < LL; k++) acc += zs[k] * wr[k];
    __nv_bfloat16 hi, lo; split_bf16(acc, hi, lo);
    g_h0hi[b * HH + h] = hi;  g_h0lo[b * HH + h] = lo;
    size_t ro = ring_off(b, h);
    g_rhi[0][ro] = hi; g_rlo[0][ro] = lo;
}

__global__ void k_seed()
{
    int i = blockIdx.x * 256 + threadIdx.x;
    int b = i >> 10, j = i & (HH - 1);
    size_t ro = ring_off(b, j);
    g_rhi[0][ro] = g_h0hi[i];
    g_rlo[0][ro] = g_h0lo[i];
}

// ---------------- layer-0 input (start token / shifted target) -> bf16 pair ----------------
__global__ void k_convin(const float* __restrict__ tgt, const float* __restrict__ start)
{
    int idx = blockIdx.x * 256 + threadIdx.x;      // over MTOT*PP
    int m = idx >> 7, p = idx & (PP - 1);
    int t = m & (TT - 1);
    float v = (t == 0) ? start[p] : tgt[(size_t)(m - 1) * PP + p];
    __nv_bfloat16 hi, lo; split_bf16(v, hi, lo);
    g_inhi[idx] = hi; g_inlo[idx] = lo;
}

// ---------------- weight matrix -> bf16 pair scratch ----------------
__global__ void k_convw(const float* __restrict__ src, int n)
{
    int i = blockIdx.x * 256 + threadIdx.x;
    if (i < n) {
        __nv_bfloat16 hi, lo; split_bf16(src[i], hi, lo);
        g_whi[i] = hi; g_wlo[i] = lo;
    }
}

// ---------------- split-bf16 GEMM (R8 scalar-LDS version; measured fastest) ----------------
template<int ACT>
__global__ __launch_bounds__(256, 2)
void k_bgemm(const __nv_bfloat16* __restrict__ Ahi, const __nv_bfloat16* __restrict__ Alo,
             const __nv_bfloat16* __restrict__ Bhi, const __nv_bfloat16* __restrict__ Blo,
             int K,
             const float* __restrict__ bias1, const float* __restrict__ bias2,
             float* __restrict__ C, int ldc)
{
    __shared__ __align__(16) __nv_bfloat16 sA[2][2][64 * 40];
    __shared__ __align__(16) __nv_bfloat16 sB[2][2][64 * 40];

    int m0 = blockIdx.x * 64, n0 = blockIdx.y * 64;
    int tid = threadIdx.x;
    int lane = tid & 31, w = tid >> 5;
    int g = lane >> 2, tg = lane & 3;
    int m0w = (w & 3) * 16, n0w = (w >> 2) * 32;

    int srow = tid >> 2, sseg = (tid & 3) * 8;
    const __nv_bfloat16* gAh = Ahi + (size_t)(m0 + srow) * K + sseg;
    const __nv_bfloat16* gAl = Alo + (size_t)(m0 + srow) * K + sseg;
    const __nv_bfloat16* gBh = Bhi + (size_t)(n0 + srow) * K + sseg;
    const __nv_bfloat16* gBl = Blo + (size_t)(n0 + srow) * K + sseg;
    int soff = srow * 40 + sseg;

    float acc[4][4];
    #pragma unroll
    for (int i = 0; i < 4; i++)
        #pragma unroll
        for (int j = 0; j < 4; j++) acc[i][j] = 0.0f;

    int nch = K >> 5;
    cp16(&sA[0][0][soff], gAh); cp16(&sA[0][1][soff], gAl);
    cp16(&sB[0][0][soff], gBh); cp16(&sB[0][1][soff], gBl);
    CP_COMMIT();

    for (int c = 0; c < nch; c++) {
        int buf = c & 1;
        if (c + 1 < nch) {
            int ko = (c + 1) * 32;
            cp16(&sA[buf ^ 1][0][soff], gAh + ko); cp16(&sA[buf ^ 1][1][soff], gAl + ko);
            cp16(&sB[buf ^ 1][0][soff], gBh + ko); cp16(&sB[buf ^ 1][1][soff], gBl + ko);
            CP_COMMIT();
            CP_WAIT1();
        } else {
            CP_WAIT0();
        }
        __syncthreads();

        const __nv_bfloat16* Ah = &sA[buf][0][0];
        const __nv_bfloat16* Al = &sA[buf][1][0];
        const __nv_bfloat16* Bh = &sB[buf][0][0];
        const __nv_bfloat16* Bl = &sB[buf][1][0];
        #pragma unroll
        for (int kk = 0; kk < 2; kk++) {
            int kb = kk * 16 + tg * 2;
            unsigned ah0 = *(const unsigned*)&Ah[(m0w + g) * 40 + kb];
            unsigned ah1 = *(const unsigned*)&Ah[(m0w + g + 8) * 40 + kb];
            unsigned ah2 = *(const unsigned*)&Ah[(m0w + g) * 40 + kb + 8];
            unsigned ah3 = *(const unsigned*)&Ah[(m0w + g + 8) * 40 + kb + 8];
            unsigned al0 = *(const unsigned*)&Al[(m0w + g) * 40 + kb];
            unsigned al1 = *(const unsigned*)&Al[(m0w + g + 8) * 40 + kb];
            unsigned al2 = *(const unsigned*)&Al[(m0w + g) * 40 + kb + 8];
            unsigned al3 = *(const unsigned*)&Al[(m0w + g + 8) * 40 + kb + 8];
            #pragma unroll
            for (int nt = 0; nt < 4; nt++) {
                int nn = (n0w + nt * 8 + g) * 40 + kb;
                unsigned bh0 = *(const unsigned*)&Bh[nn];
                unsigned bh1 = *(const unsigned*)&Bh[nn + 8];
                unsigned bl0 = *(const unsigned*)&Bl[nn];
                unsigned bl1 = *(const unsigned*)&Bl[nn + 8];
                mma16816(acc[nt], ah0, ah1, ah2, ah3, bh0, bh1);
                mma16816(acc[nt], al0, al1, al2, al3, bh0, bh1);
                mma16816(acc[nt], ah0, ah1, ah2, ah3, bl0, bl1);
            }
        }
        __syncthreads();
    }

    #pragma unroll
    for (int nt = 0; nt < 4; nt++) {
        int col = n0 + n0w + nt * 8 + tg * 2;
        float b0v = bias1[col]     + (bias2 ? bias2[col]     : 0.0f);
        float b1v = bias1[col + 1] + (bias2 ? bias2[col + 1] : 0.0f);
        float v0 = acc[nt][0] + b0v, v1 = acc[nt][1] + b1v;
        float v2 = acc[nt][2] + b0v, v3 = acc[nt][3] + b1v;
        if (ACT) { v0 = sigf(v0); v1 = sigf(v1); v2 = sigf(v2); v3 = sigf(v3); }
        int r0 = m0 + m0w + g, r1 = r0 + 8;
        *(float2*)&C[(size_t)r0 * ldc + col] = make_float2(v0, v1);
        *(float2*)&C[(size_t)r1 * ldc + col] = make_float2(v2, v3);
    }
}

// ---------------- persistent recurrence with bulk-async h staging ----------------
// 128 CTAs (1/SM, co-resident). CTA owns h-dims [j0,j0+8) -> 32 gate cols.
// Whh slice bf16 hi/lo in SMEM for whole kernel. Per 128-col K-chunk, ONE elected
// thread issues 2 x 16KB cp.async.bulk (hi/lo) from the swizzled gmem ring into
// SMEM; mbarrier completes; ldmatrix reads with the XOR pattern. Double-buffered.
#define WPITCH 1032
#define SM_WH 0
#define SM_WL 66048
#define SM_HS 132096          // [2 buf][2 half][64 rows * 256B]
#define SM_GS 197632          // [64][33] float
#define SM_CS 206080          // [512] float
#define SM_MB 208128          // 2 mbarriers
#define SMEM_PERSIST 208144

__global__ __launch_bounds__(256, 1)
void k_persist(const float* __restrict__ Whh, const float* __restrict__ xg,
               __nv_bfloat16* __restrict__ rhi, __nv_bfloat16* __restrict__ rlo,
               __nv_bfloat16* __restrict__ shi, __nv_bfloat16* __restrict__ slo)
{
    extern __shared__ char sm[];
    __nv_bfloat16* Wh  = (__nv_bfloat16*)(sm + SM_WH);
    __nv_bfloat16* Wl  = (__nv_bfloat16*)(sm + SM_WL);
    __nv_bfloat16* HsB = (__nv_bfloat16*)(sm + SM_HS);
    float* Gs = (float*)(sm + SM_GS);
    float* Cs = (float*)(sm + SM_CS);
    unsigned mbar[2];
    mbar[0] = (unsigned)__cvta_generic_to_shared(sm + SM_MB);
    mbar[1] = mbar[0] + 8;
    unsigned hsu = (unsigned)__cvta_generic_to_shared(sm + SM_HS);

    int tid = threadIdx.x;
    int lane = tid & 31, w = tid >> 5;
    int g = lane >> 2, tg = lane & 3;
    int m0w = (w >> 1) * 16, n0w = (w & 1) * 16;
    int j0 = blockIdx.x * 8;

    // ldmatrix lane addressing
    int grp = lane >> 3, lr = lane & 7;
    int ar = m0w + (grp & 1) * 8 + lr;          // batch row 0..63
    int arx = (ar & 7) << 4;                    // swizzle XOR for this row
    int axb = (grp >> 1) * 16;                  // 0 or 16 bytes (k-halves)
    int w_boff0 = ((grp >= 2) ? 32 * WPITCH : 0) + (n0w + lr) * WPITCH + (grp & 1) * 8;
    int w_boff1 = w_boff0 + 8 * WPITCH;

    // one-time: split W slice into SMEM; zero cell state; init mbarriers
    for (int s = tid; s < 32 * 256; s += 256) {
        int n = s >> 8;
        int ks = (s & 255) * 4;
        int grow = (n >> 3) * HH + j0 + (n & 7);
        float4 v = *(const float4*)&Whh[(size_t)grow * HH + ks];
        float vv[4] = {v.x, v.y, v.z, v.w};
        #pragma unroll
        for (int q = 0; q < 4; q++) {
            __nv_bfloat16 hi, lo; split_bf16(vv[q], hi, lo);
            Wh[n * WPITCH + ks + q] = hi;
            Wl[n * WPITCH + ks + q] = lo;
        }
    }
    for (int s = tid; s < 512; s += 256) Cs[s] = 0.0f;
    if (tid == 0) { mbar_init(mbar[0], 1); mbar_init(mbar[1], 1); }
    __syncthreads();

    int ph[2] = {0, 0};

    for (int t = 0; t < TT; t++) {
        const __nv_bfloat16* srcHi = rhi + (size_t)(t & 1) * BB * HH;   // swizzled blocked ring
        const __nv_bfloat16* srcLo = rlo + (size_t)(t & 1) * BB * HH;
        __nv_bfloat16* ohh = rhi + (size_t)((t & 1) ^ 1) * BB * HH;
        __nv_bfloat16* ohl = rlo + (size_t)((t & 1) ^ 1) * BB * HH;

        // xg prefetch (overlaps MMA)
        float xv[2][4];
        #pragma unroll
        for (int e = 0; e < 2; e++) {
            int p = tid + e * 256;
            int b = p >> 3, jj = p & 7;
            size_t base = ((size_t)(b * TT + t)) * GG + j0 + jj;
            #pragma unroll
            for (int q = 0; q < 4; q++) xv[e][q] = __ldg(&xg[base + (size_t)q * HH]);
        }

        float acch[2][4], accm[2][4];
        #pragma unroll
        for (int i = 0; i < 2; i++)
            #pragma unroll
            for (int j = 0; j < 4; j++) { acch[i][j] = 0.0f; accm[i][j] = 0.0f; }

        // issue chunk 0 into buf 0
        if (tid == 0) {
            mbar_expect(mbar[0], 32768);
            bulkcp(hsu + 0,     srcHi, 16384, mbar[0]);
            bulkcp(hsu + 16384, srcLo, 16384, mbar[0]);
        }

        for (int c = 0; c < 8; c++) {
            int buf = c & 1;
            if (c < 7 && tid == 0) {
                int nb = buf ^ 1;
                mbar_expect(mbar[nb], 32768);
                bulkcp(hsu + nb * 32768,         srcHi + (c + 1) * 8192, 16384, mbar[nb]);
                bulkcp(hsu + nb * 32768 + 16384, srcLo + (c + 1) * 8192, 16384, mbar[nb]);
            }
            mbar_wait(mbar[buf], ph[buf]);
            ph[buf] ^= 1;

            const __nv_bfloat16* Ah = HsB + buf * 16384;   // elements; lo at +8192
            #pragma unroll
            for (int kk = 0; kk < 8; kk++) {
                int ab = ar * 128 + (((kk * 32 + axb) ^ arx) >> 1);   // element offset
                unsigned ah0, ah1, ah2, ah3, al0, al1, al2, al3;
                ldsm_x4(ah0, ah1, ah2, ah3, Ah + ab);
                ldsm_x4(al0, al1, al2, al3, Ah + 8192 + ab);
                int kw = c * 128 + kk * 16;
                unsigned b00, b01, b02, b03, b10, b11, b12, b13;
                ldsm_x4(b00, b01, b02, b03, Wh + w_boff0 + kw);
                ldsm_x4(b10, b11, b12, b13, Wh + w_boff1 + kw);
                mma16816(acch[0], ah0, ah1, ah2, ah3, b00, b01);
                mma16816(accm[0], al0, al1, al2, al3, b00, b01);
                mma16816(accm[0], ah0, ah1, ah2, ah3, b02, b03);
                mma16816(acch[1], ah0, ah1, ah2, ah3, b10, b11);
                mma16816(accm[1], al0, al1, al2, al3, b10, b11);
                mma16816(accm[1], ah0, ah1, ah2, ah3, b12, b13);
            }
            __syncthreads();   // all warps done with buf before it is refilled at c+2
        }

        // stage Whh*h into Gs  (row=batch, col=gate*8+jj)
        #pragma unroll
        for (int nt = 0; nt < 2; nt++) {
            int col = n0w + nt * 8 + tg * 2;
            Gs[(m0w + g) * 33 + col]         = acch[nt][0] + accm[nt][0];
            Gs[(m0w + g) * 33 + col + 1]     = acch[nt][1] + accm[nt][1];
            Gs[(m0w + g + 8) * 33 + col]     = acch[nt][2] + accm[nt][2];
            Gs[(m0w + g + 8) * 33 + col + 1] = acch[nt][3] + accm[nt][3];
        }
        __syncthreads();

        // LSTM cell: 8 h-dims x 64 batches
        #pragma unroll
        for (int e = 0; e < 2; e++) {
            int p = tid + e * 256;
            int b = p >> 3, jj = p & 7;
            float gi = Gs[b * 33 + jj]      + xv[e][0];
            float gf = Gs[b * 33 + 8 + jj]  + xv[e][1];
            float gg = Gs[b * 33 + 16 + jj] + xv[e][2];
            float go = Gs[b * 33 + 24 + jj] + xv[e][3];
            float cc = sigf(gf) * Cs[p] + sigf(gi) * tanhf(gg);
            float h  = sigf(go) * tanhf(cc);
            Cs[p] = cc;
            __nv_bfloat16 hhi, hlo; split_bf16(h, hhi, hlo);
            size_t ro = ring_off(b, j0 + jj);
            st_cg_b16(ohh + ro, hhi);
            st_cg_b16(ohl + ro, hlo);
            size_t sidx = ((size_t)(b * TT + t)) * HH + j0 + jj;
            shi[sidx] = hhi;
            slo[sidx] = hlo;
        }

        // grid barrier (all 128 CTAs resident; generation counter, self-resetting count)
        __syncthreads();
        __threadfence();
        if (tid == 0) {
            unsigned my = *((volatile unsigned*)&g_barg);
            if (atomicAdd(&g_barc, 1u) == NCTA - 1) {
                g_barc = 0;
                __threadfence();
                atomicExch(&g_barg, my + 1);
            } else {
                while (*((volatile unsigned*)&g_barg) == my) __nanosleep(32);
            }
            __threadfence();
        }
        __syncthreads();
    }
}

// ---------------- launch ----------------
extern "C" void kernel_launch(void* const* d_in, const int* in_sizes, int n_in,
                              void* d_out, int out_size)
{
    (void)in_sizes; (void)n_in; (void)out_size;
    const float* z     = (const float*)d_in[0];
    const float* tgt   = (const float*)d_in[1];
    const float* fw    = (const float*)d_in[2];
    const float* fb    = (const float*)d_in[3];
    const float* start = (const float*)d_in[4];
    const float* Wih0  = (const float*)d_in[5];
    const float* Whh0  = (const float*)d_in[6];
    const float* bih0  = (const float*)d_in[7];
    const float* bhh0  = (const float*)d_in[8];
    const float* Wih1  = (const float*)d_in[9];
    const float* Whh1  = (const float*)d_in[10];
    const float* bih1  = (const float*)d_in[11];
    const float* bhh1  = (const float*)d_in[12];
    const float* outw  = (const float*)d_in[13];
    const float* outb  = (const float*)d_in[14];
    float* out = (float*)d_out;

    float* xg_p;
    __nv_bfloat16 *xhi_p, *xlo_p, *inhi_p, *inlo_p, *whi_p, *wlo_p, *rhi_p, *rlo_p;
    cudaGetSymbolAddress((void**)&xg_p,   g_xg);
    cudaGetSymbolAddress((void**)&xhi_p,  g_xhi);
    cudaGetSymbolAddress((void**)&xlo_p,  g_xlo);
    cudaGetSymbolAddress((void**)&inhi_p, g_inhi);
    cudaGetSymbolAddress((void**)&inlo_p, g_inlo);
    cudaGetSymbolAddress((void**)&whi_p,  g_whi);
    cudaGetSymbolAddress((void**)&wlo_p,  g_wlo);
    cudaGetSymbolAddress((void**)&rhi_p,  g_rhi);
    cudaGetSymbolAddress((void**)&rlo_p,  g_rlo);

    cudaFuncSetAttribute(k_persist, cudaFuncAttributeMaxDynamicSharedMemorySize, SMEM_PERSIST);

    // h0 + seed ring; layer-0 input -> bf16 pair
    k_init<<<dim3(HH / 256, BB), 256>>>(z, fw, fb);
    k_convin<<<(MTOT * PP) / 256, 256>>>(tgt, start);

    // layer 0: xg0 = x_in @ Wih0^T + b  -> recurrence
    k_convw<<<(GG * PP + 255) / 256, 256>>>(Wih0, GG * PP);
    k_bgemm<0><<<dim3(MTOT / 64, GG / 64), 256>>>(inhi_p, inlo_p, whi_p, wlo_p, PP,
                                                  bih0, bhh0, xg_p, GG);
    k_persist<<<NCTA, 256, SMEM_PERSIST>>>(Whh0, xg_p, rhi_p, rlo_p, xhi_p, xlo_p);

    // layer 1: xg1 = h1seq @ Wih1^T + b (consumes g_xhi before layer-1 overwrites it)
    k_convw<<<(GG * HH + 255) / 256, 256>>>(Wih1, GG * HH);
    k_bgemm<0><<<dim3(MTOT / 64, GG / 64), 256>>>(xhi_p, xlo_p, whi_p, wlo_p, HH,
                                                  bih1, bhh1, xg_p, GG);
    k_seed<<<(BB * HH) / 256, 256>>>();
    k_persist<<<NCTA, 256, SMEM_PERSIST>>>(Whh1, xg_p, rhi_p, rlo_p, xhi_p, xlo_p);

    // out = sigmoid(h2seq @ out_w^T + out_b)
    k_convw<<<(PP * HH + 255) / 256, 256>>>(outw, PP * HH);
    k_bgemm<1><<<dim3(MTOT / 64, PP / 64), 256>>>(xhi_p, xlo_p, whi_p, wlo_p, HH,
                                                  outb, nullptr, out, PP);
}